// round 4
// baseline (speedup 1.0000x reference)
#include <cuda_runtime.h>
#include <math.h>

// FullCliffordMeanField3DClassifier — collapsed algebra, single fused kernel.
//
// Algebra (validated R1/R2, rel_err ~3e-7):
//   pv = geoprod(pos,vel): comps {0: p.v, 4: p1v2-p2v1, 5: p1v3-p3v1, 6: p2v3-p3v2}
//   mean(geoprod(vel, mean_pv)) = geoprod(mean(vel), mean_pv)   (bilinearity)
//   interaction comps {1,2,3,7}:
//     i1 = V1*m0 - V2*m4 - V3*m5
//     i2 = V2*m0 + V1*m4 - V3*m6
//     i3 = V3*m0 + V1*m5 + V2*m6
//     i7 = V1*m6 - V2*m5 + V3*m4
//   MLP 8->64->64->2, exact-erf GELU; only W1 rows {1,2,3,7} matter.
//
// One kernel: 4096 CTAs stream x; each writes deterministic per-slice partials,
// bumps a per-batch counter; the LAST block of each batch runs that batch's MLP
// (256-thread parallel) and resets the counter for the next graph replay.

#define THREADS  256
#define NPTS     4096
#define SPLIT    4
#define CHUNK    (NPTS / SPLIT)            // 1024 points / CTA
#define PAIRS    (CHUNK / 2)               // 512 pairs
#define PPT      (PAIRS / THREADS)         // 2 pairs / thread
#define MAXB     1024

__device__ float        g_partial[MAXB * SPLIT * 8];  // [batch][slice][8]
__device__ unsigned int g_count[MAXB];                // zero-init; self-resetting

__device__ __forceinline__ float gelu_exact(float v) {
    return 0.5f * v * (1.0f + erff(v * 0.70710678118654752440f));
}

__global__ __launch_bounds__(THREADS, 4)
void cm_fused_kernel(
    const float* __restrict__ x,
    const float* __restrict__ W1, const float* __restrict__ b1,
    const float* __restrict__ W2, const float* __restrict__ b2,
    const float* __restrict__ W3, const float* __restrict__ b3,
    float* __restrict__ out)
{
    const int bb    = blockIdx.x;
    const int batch = bb / SPLIT;
    const int slice = bb % SPLIT;
    const int t     = threadIdx.x;

    // ---------------- phase 1: stream this slice, 7 running sums ----------
    const float4* __restrict__ base = reinterpret_cast<const float4*>(
        x + (size_t)batch * (size_t)(NPTS * 6) + (size_t)slice * (CHUNK * 6));

    float sdot = 0.f, s12 = 0.f, s13 = 0.f, s23 = 0.f;
    float sv1 = 0.f, sv2 = 0.f, sv3 = 0.f;

    #pragma unroll
    for (int k = 0; k < PPT; ++k) {
        const int pi = t + k * THREADS;
        const float4 f0 = base[3 * pi + 0];   // p1a p2a p3a v1a
        const float4 f1 = base[3 * pi + 1];   // v2a v3a p1b p2b
        const float4 f2 = base[3 * pi + 2];   // p3b v1b v2b v3b

        sdot += f0.x * f0.w + f0.y * f1.x + f0.z * f1.y;
        s12  += f0.x * f1.x - f0.y * f0.w;
        s13  += f0.x * f1.y - f0.z * f0.w;
        s23  += f0.y * f1.y - f0.z * f1.x;
        sv1  += f0.w; sv2 += f1.x; sv3 += f1.y;

        sdot += f1.z * f2.y + f1.w * f2.z + f2.x * f2.w;
        s12  += f1.z * f2.z - f1.w * f2.y;
        s13  += f1.z * f2.w - f2.x * f2.y;
        s23  += f1.w * f2.w - f2.x * f2.z;
        sv1  += f2.y; sv2 += f2.z; sv3 += f2.w;
    }

    #pragma unroll
    for (int off = 16; off > 0; off >>= 1) {
        sdot += __shfl_xor_sync(0xffffffffu, sdot, off);
        s12  += __shfl_xor_sync(0xffffffffu, s12,  off);
        s13  += __shfl_xor_sync(0xffffffffu, s13,  off);
        s23  += __shfl_xor_sync(0xffffffffu, s23,  off);
        sv1  += __shfl_xor_sync(0xffffffffu, sv1,  off);
        sv2  += __shfl_xor_sync(0xffffffffu, sv2,  off);
        sv3  += __shfl_xor_sync(0xffffffffu, sv3,  off);
    }

    __shared__ float red[8][7];
    __shared__ int   s_last;
    const int warp = t >> 5, lane = t & 31;
    if (lane == 0) {
        red[warp][0] = sdot; red[warp][1] = s12; red[warp][2] = s13;
        red[warp][3] = s23;  red[warp][4] = sv1; red[warp][5] = sv2;
        red[warp][6] = sv3;
    }
    __syncthreads();

    if (t == 0) {
        float r[7];
        #pragma unroll
        for (int j = 0; j < 7; ++j) {
            float a = red[0][j];
            #pragma unroll
            for (int w = 1; w < 8; ++w) a += red[w][j];
            r[j] = a;
        }
        float4* dst = reinterpret_cast<float4*>(&g_partial[bb * 8]);
        dst[0] = make_float4(r[0], r[1], r[2], r[3]);
        dst[1] = make_float4(r[4], r[5], r[6], 0.f);
        __threadfence();                       // partials visible before count
        unsigned int prev = atomicAdd(&g_count[batch], 1u);
        s_last = (prev == SPLIT - 1) ? 1 : 0;
    }
    __syncthreads();

    if (!s_last) return;

    // ---------------- phase 2: last block of this batch runs the MLP ------
    __shared__ float ii[4];
    __shared__ float h1[64];
    __shared__ float l2p[256];
    __shared__ float h2[64];

    if (t == 0) g_count[batch] = 0;            // reset for next graph replay

    if (t < 32) {
        // lane s*8+j = partial j of slice s (deterministic order)
        float v = g_partial[batch * (SPLIT * 8) + t];
        v += __shfl_xor_sync(0xffffffffu, v, 8);
        v += __shfl_xor_sync(0xffffffffu, v, 16);
        const float inv = 1.0f / (float)NPTS;
        const float m0 = __shfl_sync(0xffffffffu, v, 0) * inv;
        const float m4 = __shfl_sync(0xffffffffu, v, 1) * inv;
        const float m5 = __shfl_sync(0xffffffffu, v, 2) * inv;
        const float m6 = __shfl_sync(0xffffffffu, v, 3) * inv;
        const float V1 = __shfl_sync(0xffffffffu, v, 4) * inv;
        const float V2 = __shfl_sync(0xffffffffu, v, 5) * inv;
        const float V3 = __shfl_sync(0xffffffffu, v, 6) * inv;
        if (t == 0) {
            ii[0] = V1 * m0 - V2 * m4 - V3 * m5;   // e1
            ii[1] = V2 * m0 + V1 * m4 - V3 * m6;   // e2
            ii[2] = V3 * m0 + V1 * m5 + V2 * m6;   // e3
            ii[3] = V1 * m6 - V2 * m5 + V3 * m4;   // e123
        }
    }
    __syncthreads();

    // layer 1 (W1 rows 1,2,3,7)
    if (t < 64) {
        float a = b1[t];
        a += ii[0] * __ldg(&W1[1 * 64 + t]);
        a += ii[1] * __ldg(&W1[2 * 64 + t]);
        a += ii[2] * __ldg(&W1[3 * 64 + t]);
        a += ii[3] * __ldg(&W1[7 * 64 + t]);
        h1[t] = gelu_exact(a);
    }
    __syncthreads();

    // layer 2: output j = t&63, group g = t>>6 handles i in [16g, 16g+16)
    {
        const int j = t & 63;
        const int g = t >> 6;
        float a = 0.f;
        #pragma unroll
        for (int i = 0; i < 16; ++i) {
            const int k2 = g * 16 + i;
            a += h1[k2] * __ldg(&W2[k2 * 64 + j]);
        }
        l2p[t] = a;
    }
    __syncthreads();

    if (t < 64) {
        float a = b2[t] + l2p[t] + l2p[t + 64] + l2p[t + 128] + l2p[t + 192];
        h2[t] = gelu_exact(a);
    }
    __syncthreads();

    // layer 3: 2 outputs
    if (t < 2) {
        float a = b3[t];
        #pragma unroll
        for (int i = 0; i < 64; ++i) a += h2[i] * __ldg(&W3[i * 2 + t]);
        out[batch * 2 + t] = a;
    }
}

extern "C" void kernel_launch(void* const* d_in, const int* in_sizes, int n_in,
                              void* d_out, int out_size)
{
    const float* x  = (const float*)d_in[0];
    const float* W1 = (const float*)d_in[1];
    const float* b1 = (const float*)d_in[2];
    const float* W2 = (const float*)d_in[3];
    const float* b2 = (const float*)d_in[4];
    const float* W3 = (const float*)d_in[5];
    const float* b3 = (const float*)d_in[6];
    float* out = (float*)d_out;

    const int B = in_sizes[0] / (NPTS * 6);   // 1024
    cm_fused_kernel<<<B * SPLIT, THREADS>>>(x, W1, b1, W2, b2, W3, b3, out);
}

// round 5
// speedup vs baseline: 1.2936x; 1.2936x over previous
#include <cuda_runtime.h>
#include <math.h>

// FullCliffordMeanField3DClassifier — collapsed algebra, warp-independent
// streaming + tiny finisher.
//
// Algebra (validated, rel_err ~3e-7):
//   pv comps {0: p.v, 4: p1v2-p2v1, 5: p1v3-p3v1, 6: p2v3-p3v2}
//   mean(geoprod(vel, mean_pv)) = geoprod(mean(vel), mean_pv)
//   interaction comps {1,2,3,7}:
//     i1 = V1*m0 - V2*m4 - V3*m5
//     i2 = V2*m0 + V1*m4 - V3*m6
//     i3 = V3*m0 + V1*m5 + V2*m6
//     i7 = V1*m6 - V2*m5 + V3*m4
//   MLP 8->64->64->2, exact-erf GELU; only W1 rows {1,2,3,7} matter.
//
// Kernel A: each WARP independently reduces 128 pairs (12 LDG.128/thread),
//           warp shuffle tree only, lane0 writes 8 floats. No smem/sync/atomics.
// Kernel B: per batch, float4 shuffle-reduce the 16 warp partials + MLP.

#define THREADS   256
#define NPTS      4096
#define WPB       8                        // warps per CTA
#define SLOTS     16                       // warp-partials per batch row
#define PAIRS_W   128                      // pairs per warp
#define PPT       4                        // pairs per thread (12 float4 loads)
#define MAXB      1024

__device__ float g_partial[MAXB * SLOTS * 8];   // [batch][slot][8]

__device__ __forceinline__ float gelu_exact(float v) {
    return 0.5f * v * (1.0f + erff(v * 0.70710678118654752440f));
}

// ---------------------------------------------------------------- kernel A
__global__ __launch_bounds__(THREADS, 4)
void cm_stream_kernel(const float* __restrict__ x)
{
    const int bb   = blockIdx.x;            // 0 .. 2*B-1
    const int warp = threadIdx.x >> 5;
    const int lane = threadIdx.x & 31;
    const int batch = bb >> 1;
    const int slot  = ((bb & 1) << 3) + warp;   // 0..15 within batch

    // warp's segment: 128 pairs = 384 float4
    const float4* __restrict__ base = reinterpret_cast<const float4*>(
        x + (size_t)batch * (size_t)(NPTS * 6)) + (size_t)slot * (PAIRS_W * 3);

    float sdot = 0.f, s12 = 0.f, s13 = 0.f, s23 = 0.f;
    float sv1 = 0.f, sv2 = 0.f, sv3 = 0.f;

    #pragma unroll
    for (int k = 0; k < PPT; ++k) {
        const int pi = lane + k * 32;
        const float4 f0 = base[3 * pi + 0];   // p1a p2a p3a v1a
        const float4 f1 = base[3 * pi + 1];   // v2a v3a p1b p2b
        const float4 f2 = base[3 * pi + 2];   // p3b v1b v2b v3b

        sdot += f0.x * f0.w + f0.y * f1.x + f0.z * f1.y;
        s12  += f0.x * f1.x - f0.y * f0.w;
        s13  += f0.x * f1.y - f0.z * f0.w;
        s23  += f0.y * f1.y - f0.z * f1.x;
        sv1  += f0.w; sv2 += f1.x; sv3 += f1.y;

        sdot += f1.z * f2.y + f1.w * f2.z + f2.x * f2.w;
        s12  += f1.z * f2.z - f1.w * f2.y;
        s13  += f1.z * f2.w - f2.x * f2.y;
        s23  += f1.w * f2.w - f2.x * f2.z;
        sv1  += f2.y; sv2 += f2.z; sv3 += f2.w;
    }

    // warp-local tree only (7 interleaved chains, ~5 deps deep each)
    #pragma unroll
    for (int off = 16; off > 0; off >>= 1) {
        sdot += __shfl_xor_sync(0xffffffffu, sdot, off);
        s12  += __shfl_xor_sync(0xffffffffu, s12,  off);
        s13  += __shfl_xor_sync(0xffffffffu, s13,  off);
        s23  += __shfl_xor_sync(0xffffffffu, s23,  off);
        sv1  += __shfl_xor_sync(0xffffffffu, sv1,  off);
        sv2  += __shfl_xor_sync(0xffffffffu, sv2,  off);
        sv3  += __shfl_xor_sync(0xffffffffu, sv3,  off);
    }

    if (lane == 0) {
        float4* dst = reinterpret_cast<float4*>(
            &g_partial[((size_t)batch * SLOTS + slot) * 8]);
        dst[0] = make_float4(sdot, s12, s13, s23);
        dst[1] = make_float4(sv1, sv2, sv3, 0.f);
    }
}

// ---------------------------------------------------------------- kernel B
__global__ __launch_bounds__(64)
void cm_mlp_kernel(
    const float* __restrict__ W1, const float* __restrict__ b1,
    const float* __restrict__ W2, const float* __restrict__ b2,
    const float* __restrict__ W3, const float* __restrict__ b3,
    float* __restrict__ out)
{
    const int batch = blockIdx.x;
    const int t     = threadIdx.x;

    __shared__ float ii[4];
    __shared__ float h1[64];
    __shared__ float h2[64];

    // prefetch layer-1 operands early (independent of the reduction)
    const float w1a = __ldg(&W1[1 * 64 + t]);
    const float w1b = __ldg(&W1[2 * 64 + t]);
    const float w1c = __ldg(&W1[3 * 64 + t]);
    const float w1d = __ldg(&W1[7 * 64 + t]);
    const float b1t = __ldg(&b1[t]);

    if (t < 32) {
        // 16 slots x 8 comps = 32 float4; lane L holds float4 L.
        // even lanes: comps 0-3 of slot L/2; odd lanes: comps 4-7.
        float4 v = reinterpret_cast<const float4*>(
            &g_partial[(size_t)batch * SLOTS * 8])[t];
        #pragma unroll
        for (int off = 2; off <= 16; off <<= 1) {
            v.x += __shfl_xor_sync(0xffffffffu, v.x, off);
            v.y += __shfl_xor_sync(0xffffffffu, v.y, off);
            v.z += __shfl_xor_sync(0xffffffffu, v.z, off);
            v.w += __shfl_xor_sync(0xffffffffu, v.w, off);
        }
        // now: every even lane = totals (sdot,s12,s13,s23);
        //      every odd  lane = totals (sv1,sv2,sv3,0)
        const float inv = 1.0f / (float)NPTS;
        const float m0 = __shfl_sync(0xffffffffu, v.x, 0) * inv;
        const float m4 = __shfl_sync(0xffffffffu, v.y, 0) * inv;
        const float m5 = __shfl_sync(0xffffffffu, v.z, 0) * inv;
        const float m6 = __shfl_sync(0xffffffffu, v.w, 0) * inv;
        const float V1 = __shfl_sync(0xffffffffu, v.x, 1) * inv;
        const float V2 = __shfl_sync(0xffffffffu, v.y, 1) * inv;
        const float V3 = __shfl_sync(0xffffffffu, v.z, 1) * inv;
        if (t == 0) {
            ii[0] = V1 * m0 - V2 * m4 - V3 * m5;   // e1
            ii[1] = V2 * m0 + V1 * m4 - V3 * m6;   // e2
            ii[2] = V3 * m0 + V1 * m5 + V2 * m6;   // e3
            ii[3] = V1 * m6 - V2 * m5 + V3 * m4;   // e123
        }
    }
    __syncthreads();

    // layer 1
    {
        float a = b1t + ii[0] * w1a + ii[1] * w1b + ii[2] * w1c + ii[3] * w1d;
        h1[t] = gelu_exact(a);
    }
    __syncthreads();

    // layer 2
    {
        float a = __ldg(&b2[t]);
        #pragma unroll
        for (int i = 0; i < 64; ++i) a += h1[i] * __ldg(&W2[i * 64 + t]);
        h2[t] = gelu_exact(a);
    }
    __syncthreads();

    // layer 3
    if (t < 2) {
        float a = __ldg(&b3[t]);
        #pragma unroll
        for (int i = 0; i < 64; ++i) a += h2[i] * __ldg(&W3[i * 2 + t]);
        out[batch * 2 + t] = a;
    }
}

// ---------------------------------------------------------------- launch
extern "C" void kernel_launch(void* const* d_in, const int* in_sizes, int n_in,
                              void* d_out, int out_size)
{
    const float* x  = (const float*)d_in[0];
    const float* W1 = (const float*)d_in[1];
    const float* b1 = (const float*)d_in[2];
    const float* W2 = (const float*)d_in[3];
    const float* b2 = (const float*)d_in[4];
    const float* W3 = (const float*)d_in[5];
    const float* b3 = (const float*)d_in[6];
    float* out = (float*)d_out;

    const int B = in_sizes[0] / (NPTS * 6);   // 1024
    cm_stream_kernel<<<B * 2, THREADS>>>(x);
    cm_mlp_kernel<<<B, 64>>>(W1, b1, W2, b2, W3, b3, out);
}

// round 8
// speedup vs baseline: 1.3945x; 1.0780x over previous
#include <cuda_runtime.h>
#include <math.h>

// FullCliffordMeanField3DClassifier — collapsed algebra.
// R8 (= R6/R7 resubmit): single-wave grid-stride streaming + tiny finisher.
//
// Algebra (validated, rel_err ~3e-7):
//   pv comps {0: p.v, 4: p1v2-p2v1, 5: p1v3-p3v1, 6: p2v3-p3v2}
//   mean(geoprod(vel, mean_pv)) = geoprod(mean(vel), mean_pv)
//   interaction comps {1,2,3,7}:
//     i1 = V1*m0 - V2*m4 - V3*m5
//     i2 = V2*m0 + V1*m4 - V3*m6
//     i3 = V3*m0 + V1*m5 + V2*m6
//     i7 = V1*m6 - V2*m5 + V3*m4
//   MLP 8->64->64->2, exact-erf GELU; only W1 rows {1,2,3,7} matter.
//
// Kernel A: 592 CTAs (148 SMs x 4 resident = ONE wave). 4736 warps grid-stride
//   over 16384 warp-segments (128 pairs = 6 KB each). Loads flow continuously,
//   no interior wave transitions. Warp-local shuffle tree per segment; lane 0
//   writes 8 floats. No smem/syncthreads/atomics.
// Kernel B: per batch, float4 shuffle-reduce 16 partials + MLP (warm L2).

#define CM_THREADS   256
#define CM_NPTS      4096
#define CM_SLOTS     16                    // warp-segments per batch
#define CM_PAIRS_W   128                   // pairs per segment (6 KB)
#define CM_GRID_A    592                   // 148 * 4 = one full wave
#define CM_MAXB      1024

__device__ float cm_g_partial[CM_MAXB * CM_SLOTS * 8];   // [batch][slot][8]

__device__ __forceinline__ float cm_gelu(float v) {
    return 0.5f * v * (1.0f + erff(v * 0.70710678118654752440f));
}

// ---------------------------------------------------------------- kernel A
__global__ __launch_bounds__(CM_THREADS, 4)
void cm_stream_k(const float* __restrict__ x, int nseg)
{
    const int lane   = threadIdx.x & 31;
    const int gwarp  = blockIdx.x * (CM_THREADS / 32) + (threadIdx.x >> 5);
    const int nwarps = gridDim.x * (CM_THREADS / 32);

    for (int seg = gwarp; seg < nseg; seg += nwarps) {
        const int batch = seg >> 4;            // seg / CM_SLOTS
        const int slot  = seg & (CM_SLOTS - 1);

        const float4* __restrict__ base = reinterpret_cast<const float4*>(
            x + (size_t)batch * (size_t)(CM_NPTS * 6))
            + (size_t)slot * (CM_PAIRS_W * 3);

        float sdot = 0.f, s12 = 0.f, s13 = 0.f, s23 = 0.f;
        float sv1 = 0.f, sv2 = 0.f, sv3 = 0.f;

        #pragma unroll
        for (int k = 0; k < 4; ++k) {
            const int pi = lane + k * 32;
            const float4 f0 = base[3 * pi + 0];   // p1a p2a p3a v1a
            const float4 f1 = base[3 * pi + 1];   // v2a v3a p1b p2b
            const float4 f2 = base[3 * pi + 2];   // p3b v1b v2b v3b

            sdot += f0.x * f0.w + f0.y * f1.x + f0.z * f1.y;
            s12  += f0.x * f1.x - f0.y * f0.w;
            s13  += f0.x * f1.y - f0.z * f0.w;
            s23  += f0.y * f1.y - f0.z * f1.x;
            sv1  += f0.w; sv2 += f1.x; sv3 += f1.y;

            sdot += f1.z * f2.y + f1.w * f2.z + f2.x * f2.w;
            s12  += f1.z * f2.z - f1.w * f2.y;
            s13  += f1.z * f2.w - f2.x * f2.y;
            s23  += f1.w * f2.w - f2.x * f2.z;
            sv1  += f2.y; sv2 += f2.z; sv3 += f2.w;
        }

        #pragma unroll
        for (int off = 16; off > 0; off >>= 1) {
            sdot += __shfl_xor_sync(0xffffffffu, sdot, off);
            s12  += __shfl_xor_sync(0xffffffffu, s12,  off);
            s13  += __shfl_xor_sync(0xffffffffu, s13,  off);
            s23  += __shfl_xor_sync(0xffffffffu, s23,  off);
            sv1  += __shfl_xor_sync(0xffffffffu, sv1,  off);
            sv2  += __shfl_xor_sync(0xffffffffu, sv2,  off);
            sv3  += __shfl_xor_sync(0xffffffffu, sv3,  off);
        }

        if (lane == 0) {
            float4* dst = reinterpret_cast<float4*>(&cm_g_partial[(size_t)seg * 8]);
            dst[0] = make_float4(sdot, s12, s13, s23);
            dst[1] = make_float4(sv1, sv2, sv3, 0.f);
        }
    }
}

// ---------------------------------------------------------------- kernel B
__global__ __launch_bounds__(64)
void cm_mlp_k(
    const float* __restrict__ W1, const float* __restrict__ b1,
    const float* __restrict__ W2, const float* __restrict__ b2,
    const float* __restrict__ W3, const float* __restrict__ b3,
    float* __restrict__ out)
{
    const int batch = blockIdx.x;
    const int t     = threadIdx.x;

    __shared__ float ii[4];
    __shared__ float h1[64];
    __shared__ float h2[64];

    // prefetch layer-1 operands (independent of the reduction)
    const float w1a = __ldg(&W1[1 * 64 + t]);
    const float w1b = __ldg(&W1[2 * 64 + t]);
    const float w1c = __ldg(&W1[3 * 64 + t]);
    const float w1d = __ldg(&W1[7 * 64 + t]);
    const float b1t = __ldg(&b1[t]);

    if (t < 32) {
        // 16 slots x 8 comps = 32 float4; lane L holds float4 L.
        // even lanes: comps 0-3 of slot L/2; odd lanes: comps 4-7.
        float4 v = reinterpret_cast<const float4*>(
            &cm_g_partial[(size_t)batch * CM_SLOTS * 8])[t];
        #pragma unroll
        for (int off = 2; off <= 16; off <<= 1) {
            v.x += __shfl_xor_sync(0xffffffffu, v.x, off);
            v.y += __shfl_xor_sync(0xffffffffu, v.y, off);
            v.z += __shfl_xor_sync(0xffffffffu, v.z, off);
            v.w += __shfl_xor_sync(0xffffffffu, v.w, off);
        }
        const float inv = 1.0f / (float)CM_NPTS;
        const float m0 = __shfl_sync(0xffffffffu, v.x, 0) * inv;
        const float m4 = __shfl_sync(0xffffffffu, v.y, 0) * inv;
        const float m5 = __shfl_sync(0xffffffffu, v.z, 0) * inv;
        const float m6 = __shfl_sync(0xffffffffu, v.w, 0) * inv;
        const float V1 = __shfl_sync(0xffffffffu, v.x, 1) * inv;
        const float V2 = __shfl_sync(0xffffffffu, v.y, 1) * inv;
        const float V3 = __shfl_sync(0xffffffffu, v.z, 1) * inv;
        if (t == 0) {
            ii[0] = V1 * m0 - V2 * m4 - V3 * m5;   // e1
            ii[1] = V2 * m0 + V1 * m4 - V3 * m6;   // e2
            ii[2] = V3 * m0 + V1 * m5 + V2 * m6;   // e3
            ii[3] = V1 * m6 - V2 * m5 + V3 * m4;   // e123
        }
    }
    __syncthreads();

    // layer 1
    h1[t] = cm_gelu(b1t + ii[0] * w1a + ii[1] * w1b + ii[2] * w1c + ii[3] * w1d);
    __syncthreads();

    // layer 2
    {
        float a = __ldg(&b2[t]);
        #pragma unroll
        for (int i = 0; i < 64; ++i) a += h1[i] * __ldg(&W2[i * 64 + t]);
        h2[t] = cm_gelu(a);
    }
    __syncthreads();

    // layer 3
    if (t < 2) {
        float a = __ldg(&b3[t]);
        #pragma unroll
        for (int i = 0; i < 64; ++i) a += h2[i] * __ldg(&W3[i * 2 + t]);
        out[batch * 2 + t] = a;
    }
}

// ---------------------------------------------------------------- launch
extern "C" void kernel_launch(void* const* d_in, const int* in_sizes, int n_in,
                              void* d_out, int out_size)
{
    const float* x  = (const float*)d_in[0];
    const float* W1 = (const float*)d_in[1];
    const float* b1 = (const float*)d_in[2];
    const float* W2 = (const float*)d_in[3];
    const float* b2 = (const float*)d_in[4];
    const float* W3 = (const float*)d_in[5];
    const float* b3 = (const float*)d_in[6];
    float* out = (float*)d_out;

    const int B = in_sizes[0] / (CM_NPTS * 6);   // 1024
    cm_stream_k<<<CM_GRID_A, CM_THREADS>>>(x, B * CM_SLOTS);
    cm_mlp_k<<<B, 64>>>(W1, b1, W2, b2, W3, b3, out);
}

// round 9
// speedup vs baseline: 1.4228x; 1.0203x over previous
#include <cuda_runtime.h>
#include <math.h>

// FullCliffordMeanField3DClassifier — collapsed algebra.
// R8 (= R6/R7 resubmit): single-wave grid-stride streaming + tiny finisher.
//
// Algebra (validated, rel_err ~3e-7):
//   pv comps {0: p.v, 4: p1v2-p2v1, 5: p1v3-p3v1, 6: p2v3-p3v2}
//   mean(geoprod(vel, mean_pv)) = geoprod(mean(vel), mean_pv)
//   interaction comps {1,2,3,7}:
//     i1 = V1*m0 - V2*m4 - V3*m5
//     i2 = V2*m0 + V1*m4 - V3*m6
//     i3 = V3*m0 + V1*m5 + V2*m6
//     i7 = V1*m6 - V2*m5 + V3*m4
//   MLP 8->64->64->2, exact-erf GELU; only W1 rows {1,2,3,7} matter.
//
// Kernel A: 592 CTAs (148 SMs x 4 resident = ONE wave). 4736 warps grid-stride
//   over 16384 warp-segments (128 pairs = 6 KB each). Loads flow continuously,
//   no interior wave transitions. Warp-local shuffle tree per segment; lane 0
//   writes 8 floats. No smem/syncthreads/atomics.
// Kernel B: per batch, float4 shuffle-reduce 16 partials + MLP (warm L2).

#define CM_THREADS   256
#define CM_NPTS      4096
#define CM_SLOTS     16                    // warp-segments per batch
#define CM_PAIRS_W   128                   // pairs per segment (6 KB)
#define CM_GRID_A    592                   // 148 * 4 = one full wave
#define CM_MAXB      1024

__device__ float cm_g_partial[CM_MAXB * CM_SLOTS * 8];   // [batch][slot][8]

__device__ __forceinline__ float cm_gelu(float v) {
    return 0.5f * v * (1.0f + erff(v * 0.70710678118654752440f));
}

// ---------------------------------------------------------------- kernel A
__global__ __launch_bounds__(CM_THREADS, 4)
void cm_stream_k(const float* __restrict__ x, int nseg)
{
    const int lane   = threadIdx.x & 31;
    const int gwarp  = blockIdx.x * (CM_THREADS / 32) + (threadIdx.x >> 5);
    const int nwarps = gridDim.x * (CM_THREADS / 32);

    for (int seg = gwarp; seg < nseg; seg += nwarps) {
        const int batch = seg >> 4;            // seg / CM_SLOTS
        const int slot  = seg & (CM_SLOTS - 1);

        const float4* __restrict__ base = reinterpret_cast<const float4*>(
            x + (size_t)batch * (size_t)(CM_NPTS * 6))
            + (size_t)slot * (CM_PAIRS_W * 3);

        float sdot = 0.f, s12 = 0.f, s13 = 0.f, s23 = 0.f;
        float sv1 = 0.f, sv2 = 0.f, sv3 = 0.f;

        #pragma unroll
        for (int k = 0; k < 4; ++k) {
            const int pi = lane + k * 32;
            const float4 f0 = base[3 * pi + 0];   // p1a p2a p3a v1a
            const float4 f1 = base[3 * pi + 1];   // v2a v3a p1b p2b
            const float4 f2 = base[3 * pi + 2];   // p3b v1b v2b v3b

            sdot += f0.x * f0.w + f0.y * f1.x + f0.z * f1.y;
            s12  += f0.x * f1.x - f0.y * f0.w;
            s13  += f0.x * f1.y - f0.z * f0.w;
            s23  += f0.y * f1.y - f0.z * f1.x;
            sv1  += f0.w; sv2 += f1.x; sv3 += f1.y;

            sdot += f1.z * f2.y + f1.w * f2.z + f2.x * f2.w;
            s12  += f1.z * f2.z - f1.w * f2.y;
            s13  += f1.z * f2.w - f2.x * f2.y;
            s23  += f1.w * f2.w - f2.x * f2.z;
            sv1  += f2.y; sv2 += f2.z; sv3 += f2.w;
        }

        #pragma unroll
        for (int off = 16; off > 0; off >>= 1) {
            sdot += __shfl_xor_sync(0xffffffffu, sdot, off);
            s12  += __shfl_xor_sync(0xffffffffu, s12,  off);
            s13  += __shfl_xor_sync(0xffffffffu, s13,  off);
            s23  += __shfl_xor_sync(0xffffffffu, s23,  off);
            sv1  += __shfl_xor_sync(0xffffffffu, sv1,  off);
            sv2  += __shfl_xor_sync(0xffffffffu, sv2,  off);
            sv3  += __shfl_xor_sync(0xffffffffu, sv3,  off);
        }

        if (lane == 0) {
            float4* dst = reinterpret_cast<float4*>(&cm_g_partial[(size_t)seg * 8]);
            dst[0] = make_float4(sdot, s12, s13, s23);
            dst[1] = make_float4(sv1, sv2, sv3, 0.f);
        }
    }
}

// ---------------------------------------------------------------- kernel B
__global__ __launch_bounds__(64)
void cm_mlp_k(
    const float* __restrict__ W1, const float* __restrict__ b1,
    const float* __restrict__ W2, const float* __restrict__ b2,
    const float* __restrict__ W3, const float* __restrict__ b3,
    float* __restrict__ out)
{
    const int batch = blockIdx.x;
    const int t     = threadIdx.x;

    __shared__ float ii[4];
    __shared__ float h1[64];
    __shared__ float h2[64];

    // prefetch layer-1 operands (independent of the reduction)
    const float w1a = __ldg(&W1[1 * 64 + t]);
    const float w1b = __ldg(&W1[2 * 64 + t]);
    const float w1c = __ldg(&W1[3 * 64 + t]);
    const float w1d = __ldg(&W1[7 * 64 + t]);
    const float b1t = __ldg(&b1[t]);

    if (t < 32) {
        // 16 slots x 8 comps = 32 float4; lane L holds float4 L.
        // even lanes: comps 0-3 of slot L/2; odd lanes: comps 4-7.
        float4 v = reinterpret_cast<const float4*>(
            &cm_g_partial[(size_t)batch * CM_SLOTS * 8])[t];
        #pragma unroll
        for (int off = 2; off <= 16; off <<= 1) {
            v.x += __shfl_xor_sync(0xffffffffu, v.x, off);
            v.y += __shfl_xor_sync(0xffffffffu, v.y, off);
            v.z += __shfl_xor_sync(0xffffffffu, v.z, off);
            v.w += __shfl_xor_sync(0xffffffffu, v.w, off);
        }
        const float inv = 1.0f / (float)CM_NPTS;
        const float m0 = __shfl_sync(0xffffffffu, v.x, 0) * inv;
        const float m4 = __shfl_sync(0xffffffffu, v.y, 0) * inv;
        const float m5 = __shfl_sync(0xffffffffu, v.z, 0) * inv;
        const float m6 = __shfl_sync(0xffffffffu, v.w, 0) * inv;
        const float V1 = __shfl_sync(0xffffffffu, v.x, 1) * inv;
        const float V2 = __shfl_sync(0xffffffffu, v.y, 1) * inv;
        const float V3 = __shfl_sync(0xffffffffu, v.z, 1) * inv;
        if (t == 0) {
            ii[0] = V1 * m0 - V2 * m4 - V3 * m5;   // e1
            ii[1] = V2 * m0 + V1 * m4 - V3 * m6;   // e2
            ii[2] = V3 * m0 + V1 * m5 + V2 * m6;   // e3
            ii[3] = V1 * m6 - V2 * m5 + V3 * m4;   // e123
        }
    }
    __syncthreads();

    // layer 1
    h1[t] = cm_gelu(b1t + ii[0] * w1a + ii[1] * w1b + ii[2] * w1c + ii[3] * w1d);
    __syncthreads();

    // layer 2
    {
        float a = __ldg(&b2[t]);
        #pragma unroll
        for (int i = 0; i < 64; ++i) a += h1[i] * __ldg(&W2[i * 64 + t]);
        h2[t] = cm_gelu(a);
    }
    __syncthreads();

    // layer 3
    if (t < 2) {
        float a = __ldg(&b3[t]);
        #pragma unroll
        for (int i = 0; i < 64; ++i) a += h2[i] * __ldg(&W3[i * 2 + t]);
        out[batch * 2 + t] = a;
    }
}

// ---------------------------------------------------------------- launch
extern "C" void kernel_launch(void* const* d_in, const int* in_sizes, int n_in,
                              void* d_out, int out_size)
{
    const float* x  = (const float*)d_in[0];
    const float* W1 = (const float*)d_in[1];
    const float* b1 = (const float*)d_in[2];
    const float* W2 = (const float*)d_in[3];
    const float* b2 = (const float*)d_in[4];
    const float* W3 = (const float*)d_in[5];
    const float* b3 = (const float*)d_in[6];
    float* out = (float*)d_out;

    const int B = in_sizes[0] / (CM_NPTS * 6);   // 1024
    cm_stream_k<<<CM_GRID_A, CM_THREADS>>>(x, B * CM_SLOTS);
    cm_mlp_k<<<B, 64>>>(W1, b1, W2, b2, W3, b3, out);
}